// round 13
// baseline (speedup 1.0000x reference)
#include <cuda_runtime.h>
#include <cooperative_groups.h>
#include <math_constants.h>

namespace cg = cooperative_groups;

#define NCH   64
#define NPIX  16384      // 128*128
#define BINS  256
#define CSEG  4          // CTAs per channel (cluster size) in K1
#define LSEG  16         // blocks per channel in K2
#define SLICE_K (NPIX / CSEG)   // 4096
#define SLICE_L (NPIX / LSEG)   // 1024
#define GRID2  (NCH * LSEG)     // 1024
#define TICK_STRIDE 64          // 64 uints = 256B between channel tickets

__device__ float    g_cdf[NCH][BINS];    // per-channel inclusive cdf (exact ints in fp32)
__device__ float    g_r0[BINS];          // finished channel-0 correction row
__device__ float    g_msum;
__device__ float    g_ls[GRID2];
__device__ unsigned g_tick_ch[NCH * TICK_STRIDE];  // zero-initialized
__device__ unsigned g_tick_top = 0;

__device__ __forceinline__ float warpSum(float v){
    #pragma unroll
    for (int o = 16; o; o >>= 1) v += __shfl_down_sync(0xffffffffu, v, o);
    return v;
}
__device__ __forceinline__ float warpMin(float v){
    #pragma unroll
    for (int o = 16; o; o >>= 1) v = fminf(v, __shfl_down_sync(0xffffffffu, v, o));
    return v;
}
__device__ __forceinline__ float warpMax(float v){
    #pragma unroll
    for (int o = 16; o; o >>= 1) v = fmaxf(v, __shfl_down_sync(0xffffffffu, v, o));
    return v;
}

// ───────── K1: per-channel min/max + histogram + cdf scan (cluster of 4 CTAs/channel);
//              cluster 0 additionally builds and publishes r0 ─────────
__global__ void __cluster_dims__(CSEG, 1, 1) __launch_bounds__(256) k_hist_k(
    const float* __restrict__ input,
    const float* __restrict__ match,
    const float* __restrict__ mask)
{
    cg::cluster_group cluster = cg::this_cluster();
    const int c    = blockIdx.x / CSEG;               // channel
    const int seg  = (int)cluster.block_rank();       // 0..3
    const int t    = threadIdx.x;
    const int lane = t & 31, w = t >> 5;
    const int base = seg * SLICE_K;

    __shared__ float sred[8][5];
    __shared__ float s_stat[8];   // [0]mnM [1]mxM [2]mnX0 [3]mxX0 [4]msum [5]mn [6]safe_w
    __shared__ int   s_hist[BINS];
    __shared__ float s_cdf[BINS];
    __shared__ float s_sc[8];

    s_hist[t] = 0;

    // Phase A: per-CTA min/max of match*mask (+ ch0 input stats / mask sum)
    {
        const float4* __restrict__ m4 = (const float4*)(match + c * NPIX + base);
        const float4* __restrict__ k4 = (const float4*)(mask + base);
        const float4* __restrict__ x4 = (const float4*)(input + base);   // channel 0

        float mnM =  CUDART_INF_F, mxM = -CUDART_INF_F;
        float mnX =  CUDART_INF_F, mxX = -CUDART_INF_F;
        float ms  = 0.f;

        #pragma unroll
        for (int k = 0; k < SLICE_K / (256 * 4); k++) {
            const int i = t + 256 * k;
            float4 a = m4[i], bb = k4[i];
            float p0 = a.x * bb.x, p1 = a.y * bb.y, p2 = a.z * bb.z, p3 = a.w * bb.w;
            mnM = fminf(fminf(mnM, p0), fminf(p1, fminf(p2, p3)));
            mxM = fmaxf(fmaxf(mxM, p0), fmaxf(p1, fmaxf(p2, p3)));
            if (c == 0) {
                float4 xv = x4[i];
                float q0 = xv.x * bb.x, q1 = xv.y * bb.y, q2 = xv.z * bb.z, q3 = xv.w * bb.w;
                mnX = fminf(fminf(mnX, q0), fminf(q1, fminf(q2, q3)));
                mxX = fmaxf(fmaxf(mxX, q0), fmaxf(q1, fmaxf(q2, q3)));
                ms += (bb.x + bb.y) + (bb.z + bb.w);
            }
        }

        mnM = warpMin(mnM);  mxM = warpMax(mxM);
        mnX = warpMin(mnX);  mxX = warpMax(mxX);
        ms  = warpSum(ms);
        if (lane == 0) {
            sred[w][0] = mnM; sred[w][1] = mxM;
            sred[w][2] = mnX; sred[w][3] = mxX;
            sred[w][4] = ms;
        }
        __syncthreads();
        if (t == 0) {
            float a = sred[0][0], bb = sred[0][1];
            float d = sred[0][2], e = sred[0][3];
            float f = sred[0][4];
            #pragma unroll
            for (int i = 1; i < 8; i++) {
                a = fminf(a, sred[i][0]); bb = fmaxf(bb, sred[i][1]);
                d = fminf(d, sred[i][2]); e  = fmaxf(e,  sred[i][3]);
                f += sred[i][4];
            }
            s_stat[0] = a;  s_stat[1] = bb;
            s_stat[2] = d;  s_stat[3] = e;  s_stat[4] = f;
        }
    }

    cluster.sync();

    // Merge channel min/max across the 4 CTAs via DSMEM
    if (t == 0) {
        float a =  CUDART_INF_F, bb = -CUDART_INF_F;
        #pragma unroll
        for (int r = 0; r < CSEG; r++) {
            const float* p = cluster.map_shared_rank((const float*)s_stat, r);
            a  = fminf(a,  p[0]);
            bb = fmaxf(bb, p[1]);
        }
        float wM = (bb - a) / (float)BINS;
        s_stat[5] = a;
        s_stat[6] = (wM > 0.f) ? wM : 1.0f;   // torch.histc safe width
    }
    __syncthreads();

    // Phase B: histogram of this CTA's slice (match/mask warm in L1/L2)
    {
        const float mn = s_stat[5], wS = s_stat[6];
        const float4* __restrict__ m4 = (const float4*)(match + c * NPIX + base);
        const float4* __restrict__ k4 = (const float4*)(mask + base);

        #pragma unroll
        for (int k = 0; k < SLICE_K / (256 * 4); k++) {
            const int i = t + 256 * k;
            float4 a = m4[i], bb = k4[i];
            float p[4] = {a.x * bb.x, a.y * bb.y, a.z * bb.z, a.w * bb.w};
            #pragma unroll
            for (int j = 0; j < 4; j++) {
                int bi = (int)floorf((p[j] - mn) / wS);
                bi = min(BINS - 1, max(0, bi));
                atomicAdd(&s_hist[bi], 1);
            }
        }
    }
    __syncthreads();
    cluster.sync();

    // Rank 0: merge the 4 smem histograms via DSMEM, scan, publish cdf (+ r0 on ch 0)
    if (seg == 0) {
        int sum = s_hist[t];
        #pragma unroll
        for (int r = 1; r < CSEG; r++) {
            const int* ph = cluster.map_shared_rank((const int*)s_hist, r);
            sum += ph[t];
        }

        // warp-shuffle inclusive scan of 256 exact-int counts
        float v = (float)sum;
        #pragma unroll
        for (int o = 1; o < 32; o <<= 1) {
            float n = __shfl_up_sync(0xffffffffu, v, o);
            if (lane >= o) v += n;
        }
        if (lane == 31) s_sc[w] = v;
        __syncthreads();
        if (w == 0) {
            float x = (lane < 8) ? s_sc[lane] : 0.f;
            #pragma unroll
            for (int o = 1; o < 8; o <<= 1) {
                float n = __shfl_up_sync(0xffffffffu, x, o);
                if (lane >= o) x += n;
            }
            if (lane < 8) s_sc[lane] = x;
        }
        __syncthreads();
        if (w > 0) v += s_sc[w - 1];
        g_cdf[c][t] = v;

        // Cluster 0 only: finish ch-0 stats, build & publish r0
        if (c == 0) {
            s_cdf[t] = v;
            if (t == 0) {
                float d = s_stat[2], e = s_stat[3], f = s_stat[4];
                #pragma unroll
                for (int r = 1; r < CSEG; r++) {
                    const float* p = cluster.map_shared_rank((const float*)s_stat, r);
                    d = fminf(d, p[2]);
                    e = fmaxf(e, p[3]);
                    f += p[4];
                }
                s_stat[2] = d;                       // min0
                s_stat[3] = (e - d) / (float)BINS;   // step0
                g_msum = f;
            }
            __syncthreads();

            // r0[j] from CHANNEL-0 quantities (faithful flattened-gather semantics)
            const float rank = (float)(t + 1);
            int lo = 0, hi = BINS;
            #pragma unroll
            for (int it = 0; it < 8; it++) {
                int mid = (lo + hi) >> 1;
                if (s_cdf[mid] < rank) lo = mid + 1; else hi = mid;
            }
            const float prev = lo ? s_cdf[lo - 1] : 0.f;
            float ratio = (rank - prev) / (1e-8f + s_cdf[lo]);
            ratio = fminf(1.f, fmaxf(0.f, ratio));
            g_r0[t] = s_stat[2] + (ratio + (float)lo) * s_stat[3];
        }
    }

    cluster.sync();   // keep peer CTAs alive until rank-0 DSMEM reads finish
}

// ───────── K2: loss + hierarchical-ticket finalize ─────────
__global__ void __launch_bounds__(256) k_loss(
    const float* __restrict__ input,
    const float* __restrict__ mask,
    float* __restrict__ out)
{
    const int b   = blockIdx.x;
    const int c   = b / LSEG;
    const int seg = b % LSEG;
    const int t   = threadIdx.x;
    const int lane = t & 31, w = t >> 5;

    __shared__ float cdfc[BINS], r0s[BINS];
    __shared__ float sw_[8];
    __shared__ bool  is_last;

    // Prologue: just two smem fills (cdf precomputed in K1)
    cdfc[t] = g_cdf[c][t];
    r0s[t]  = g_r0[t];
    __syncthreads();

    // Loss over this block's 1024-element slice: one float4 per thread
    const int base = seg * SLICE_L;
    const float4* __restrict__ x4 = (const float4*)(input + c * NPIX + base);
    const float4* __restrict__ k4 = (const float4*)(mask + base);

    float acc;
    {
        float4 xv = x4[t], mk = k4[t];
        const int n0 = base + t * 4;
        float xs[4] = {xv.x * mk.x, xv.y * mk.y, xv.z * mk.z, xv.w * mk.w};

        int lo = 0, hi = BINS;
        const float rank0 = (float)(n0 + 1);
        #pragma unroll
        for (int it = 0; it < 8; it++) {
            int mid = (lo + hi) >> 1;
            if (cdfc[mid] < rank0) lo = mid + 1; else hi = mid;
        }
        acc = 0.f;
        #pragma unroll
        for (int j = 0; j < 4; j++) {
            const float rank = (float)(n0 + j + 1);
            while (lo < BINS - 1 && cdfc[lo] < rank) lo++;
            const float d = r0s[lo] - xs[j];
            acc += d * d;
        }
    }

    acc = warpSum(acc);
    if (lane == 0) sw_[w] = acc;
    __syncthreads();
    if (t == 0) {
        float s = 0.f;
        #pragma unroll
        for (int i = 0; i < 8; i++) s += sw_[i];
        g_ls[b] = s;
    }

    // Hierarchical ticket: channel-level (16 contenders, 64 distinct addresses),
    // then top-level (64 contenders). Avoids 1024-way single-address serialization.
    __threadfence();
    __syncthreads();
    if (t == 0) {
        is_last = false;
        unsigned k = atomicAdd(&g_tick_ch[c * TICK_STRIDE], 1u);
        if (k == LSEG - 1) {
            atomicExch(&g_tick_ch[c * TICK_STRIDE], 0u);   // reset for next replay
            unsigned kt = atomicAdd(&g_tick_top, 1u);
            if (kt == NCH - 1) {
                atomicExch(&g_tick_top, 0u);               // reset for next replay
                is_last = true;
            }
        }
    }
    __syncthreads();
    if (is_last) {
        float s4 = __ldcg(&g_ls[t])       + __ldcg(&g_ls[t + 256])
                 + __ldcg(&g_ls[t + 512]) + __ldcg(&g_ls[t + 768]);
        s4 = warpSum(s4);
        if (lane == 0) sw_[w] = s4;
        __syncthreads();
        if (t == 0) {
            float s = 0.f;
            #pragma unroll
            for (int i = 0; i < 8; i++) s += sw_[i];
            const float size = (float)(NCH * NPIX);
            out[0] = (s / size) * __ldcg(&g_msum) * (float)NCH / size;  // * WEIGHT (=1.0)
        }
    }
}

extern "C" void kernel_launch(void* const* d_in, const int* in_sizes, int n_in,
                              void* d_out, int out_size)
{
    const float* input = (const float*)d_in[0];
    const float* match = (const float*)d_in[1];
    const float* mask  = (const float*)d_in[2];

    k_hist_k<<<NCH * CSEG, 256>>>(input, match, mask);
    k_loss  <<<GRID2, 256>>>(input, mask, (float*)d_out);
}

// round 14
// speedup vs baseline: 1.1800x; 1.1800x over previous
#include <cuda_runtime.h>
#include <cooperative_groups.h>
#include <math_constants.h>

namespace cg = cooperative_groups;

#define NCH   64
#define NPIX  16384      // 128*128
#define BINS  256
#define CSEG  4          // CTAs per channel (cluster size) in K1
#define LSEG  16         // blocks per channel in K2
#define SLICE_K (NPIX / CSEG)   // 4096
#define SLICE_L (NPIX / LSEG)   // 1024
#define GRID2  (NCH * LSEG)     // 1024

__device__ float g_cdf[NCH][BINS];    // per-channel inclusive cdf (exact ints in fp32)
__device__ float g_r0[BINS];          // finished channel-0 correction row
__device__ float g_msum;

__device__ __forceinline__ float warpSum(float v){
    #pragma unroll
    for (int o = 16; o; o >>= 1) v += __shfl_down_sync(0xffffffffu, v, o);
    return v;
}
__device__ __forceinline__ float warpMin(float v){
    #pragma unroll
    for (int o = 16; o; o >>= 1) v = fminf(v, __shfl_down_sync(0xffffffffu, v, o));
    return v;
}
__device__ __forceinline__ float warpMax(float v){
    #pragma unroll
    for (int o = 16; o; o >>= 1) v = fmaxf(v, __shfl_down_sync(0xffffffffu, v, o));
    return v;
}

// ───────── K1: single-pass per-channel min/max + histogram + cdf (cluster of 4/channel);
//              cluster 0 additionally builds and publishes r0. Zeroes out[0]. ─────────
__global__ void __cluster_dims__(CSEG, 1, 1) __launch_bounds__(256) k_hist_k(
    const float* __restrict__ input,
    const float* __restrict__ match,
    const float* __restrict__ mask,
    float* __restrict__ out)
{
    // Let the PDL-dependent k_loss start fetching its inputs ASAP.
    cudaTriggerProgrammaticLaunchCompletion();

    cg::cluster_group cluster = cg::this_cluster();
    const int c    = blockIdx.x / CSEG;               // channel
    const int seg  = (int)cluster.block_rank();       // 0..3
    const int t    = threadIdx.x;
    const int lane = t & 31, w = t >> 5;
    const int base = seg * SLICE_K;

    if (blockIdx.x == 0 && t == 0) out[0] = 0.f;      // K2 accumulates into out

    __shared__ float sred[8][5];
    __shared__ float s_stat[8];   // [0]mnM [1]mxM [2]mnX0 [3]mxX0 [4]msum [5]mn [6]safe_w
    __shared__ int   s_hist[BINS];
    __shared__ float s_cdf[BINS];
    __shared__ float s_sc[8];

    s_hist[t] = 0;

    // Phase A: one global pass; keep match*mask products in registers
    float4 pm[SLICE_K / (256 * 4)];                   // 4 x float4 = 16 floats
    {
        const float4* __restrict__ m4 = (const float4*)(match + c * NPIX + base);
        const float4* __restrict__ k4 = (const float4*)(mask + base);
        const float4* __restrict__ x4 = (const float4*)(input + base);   // channel 0

        float mnM =  CUDART_INF_F, mxM = -CUDART_INF_F;
        float mnX =  CUDART_INF_F, mxX = -CUDART_INF_F;
        float ms  = 0.f;

        #pragma unroll
        for (int k = 0; k < SLICE_K / (256 * 4); k++) {
            const int i = t + 256 * k;
            float4 a = m4[i], bb = k4[i];
            float4 p;
            p.x = a.x * bb.x; p.y = a.y * bb.y; p.z = a.z * bb.z; p.w = a.w * bb.w;
            pm[k] = p;
            mnM = fminf(fminf(mnM, p.x), fminf(p.y, fminf(p.z, p.w)));
            mxM = fmaxf(fmaxf(mxM, p.x), fmaxf(p.y, fmaxf(p.z, p.w)));
            if (c == 0) {
                float4 xv = x4[i];
                float q0 = xv.x * bb.x, q1 = xv.y * bb.y, q2 = xv.z * bb.z, q3 = xv.w * bb.w;
                mnX = fminf(fminf(mnX, q0), fminf(q1, fminf(q2, q3)));
                mxX = fmaxf(fmaxf(mxX, q0), fmaxf(q1, fmaxf(q2, q3)));
                ms += (bb.x + bb.y) + (bb.z + bb.w);
            }
        }

        mnM = warpMin(mnM);  mxM = warpMax(mxM);
        mnX = warpMin(mnX);  mxX = warpMax(mxX);
        ms  = warpSum(ms);
        if (lane == 0) {
            sred[w][0] = mnM; sred[w][1] = mxM;
            sred[w][2] = mnX; sred[w][3] = mxX;
            sred[w][4] = ms;
        }
        __syncthreads();
        if (t == 0) {
            float a = sred[0][0], bb = sred[0][1];
            float d = sred[0][2], e = sred[0][3];
            float f = sred[0][4];
            #pragma unroll
            for (int i = 1; i < 8; i++) {
                a = fminf(a, sred[i][0]); bb = fmaxf(bb, sred[i][1]);
                d = fminf(d, sred[i][2]); e  = fmaxf(e,  sred[i][3]);
                f += sred[i][4];
            }
            s_stat[0] = a;  s_stat[1] = bb;
            s_stat[2] = d;  s_stat[3] = e;  s_stat[4] = f;
        }
    }

    cluster.sync();

    // Merge channel min/max across the 4 CTAs via DSMEM
    if (t == 0) {
        float a =  CUDART_INF_F, bb = -CUDART_INF_F;
        #pragma unroll
        for (int r = 0; r < CSEG; r++) {
            const float* p = cluster.map_shared_rank((const float*)s_stat, r);
            a  = fminf(a,  p[0]);
            bb = fmaxf(bb, p[1]);
        }
        float wM = (bb - a) / (float)BINS;
        s_stat[5] = a;
        s_stat[6] = (wM > 0.f) ? wM : 1.0f;   // torch.histc safe width
    }
    __syncthreads();

    // Phase B: histogram straight from registers (no second global pass)
    {
        const float mn = s_stat[5], wS = s_stat[6];
        #pragma unroll
        for (int k = 0; k < SLICE_K / (256 * 4); k++) {
            float p[4] = {pm[k].x, pm[k].y, pm[k].z, pm[k].w};
            #pragma unroll
            for (int j = 0; j < 4; j++) {
                int bi = (int)floorf((p[j] - mn) / wS);
                bi = min(BINS - 1, max(0, bi));
                atomicAdd(&s_hist[bi], 1);
            }
        }
    }
    __syncthreads();
    cluster.sync();

    // Rank 0: merge the 4 smem histograms via DSMEM, scan, publish cdf (+ r0 on ch 0)
    if (seg == 0) {
        int sum = s_hist[t];
        #pragma unroll
        for (int r = 1; r < CSEG; r++) {
            const int* ph = cluster.map_shared_rank((const int*)s_hist, r);
            sum += ph[t];
        }

        // warp-shuffle inclusive scan of 256 exact-int counts
        float v = (float)sum;
        #pragma unroll
        for (int o = 1; o < 32; o <<= 1) {
            float n = __shfl_up_sync(0xffffffffu, v, o);
            if (lane >= o) v += n;
        }
        if (lane == 31) s_sc[w] = v;
        __syncthreads();
        if (w == 0) {
            float x = (lane < 8) ? s_sc[lane] : 0.f;
            #pragma unroll
            for (int o = 1; o < 8; o <<= 1) {
                float n = __shfl_up_sync(0xffffffffu, x, o);
                if (lane >= o) x += n;
            }
            if (lane < 8) s_sc[lane] = x;
        }
        __syncthreads();
        if (w > 0) v += s_sc[w - 1];
        g_cdf[c][t] = v;

        // Cluster 0 only: finish ch-0 stats, build & publish r0
        if (c == 0) {
            s_cdf[t] = v;
            if (t == 0) {
                float d = s_stat[2], e = s_stat[3], f = s_stat[4];
                #pragma unroll
                for (int r = 1; r < CSEG; r++) {
                    const float* p = cluster.map_shared_rank((const float*)s_stat, r);
                    d = fminf(d, p[2]);
                    e = fmaxf(e, p[3]);
                    f += p[4];
                }
                s_stat[2] = d;                       // min0
                s_stat[3] = (e - d) / (float)BINS;   // step0
                g_msum = f;
            }
            __syncthreads();

            // r0[j] from CHANNEL-0 quantities (faithful flattened-gather semantics)
            const float rank = (float)(t + 1);
            int lo = 0, hi = BINS;
            #pragma unroll
            for (int it = 0; it < 8; it++) {
                int mid = (lo + hi) >> 1;
                if (s_cdf[mid] < rank) lo = mid + 1; else hi = mid;
            }
            const float prev = lo ? s_cdf[lo - 1] : 0.f;
            float ratio = (rank - prev) / (1e-8f + s_cdf[lo]);
            ratio = fminf(1.f, fmaxf(0.f, ratio));
            g_r0[t] = s_stat[2] + (ratio + (float)lo) * s_stat[3];
        }
    }

    cluster.sync();   // keep peer CTAs alive until rank-0 DSMEM reads finish
}

// ───────── K2 (PDL secondary): prefetch inputs, sync on K1, loss, atomicAdd out ─────────
__global__ void __launch_bounds__(256) k_loss(
    const float* __restrict__ input,
    const float* __restrict__ mask,
    float* __restrict__ out)
{
    const int b   = blockIdx.x;
    const int c   = b / LSEG;
    const int seg = b % LSEG;
    const int t   = threadIdx.x;
    const int lane = t & 31, w = t >> 5;
    const int base = seg * SLICE_L;

    // Prefetch this block's data BEFORE depending on K1's outputs.
    const float4* __restrict__ x4 = (const float4*)(input + c * NPIX + base);
    const float4* __restrict__ k4 = (const float4*)(mask + base);
    float4 xv = x4[t];
    float4 mk = k4[t];

    // Wait for K1 completion (makes g_cdf / g_r0 / g_msum / out=0 visible).
    cudaGridDependencySynchronize();

    __shared__ float cdfc[BINS], r0s[BINS];
    __shared__ float sw_[8];
    cdfc[t] = g_cdf[c][t];
    r0s[t]  = g_r0[t];
    __syncthreads();

    float acc;
    {
        const int n0 = base + t * 4;
        float xs[4] = {xv.x * mk.x, xv.y * mk.y, xv.z * mk.z, xv.w * mk.w};

        int lo = 0, hi = BINS;
        const float rank0 = (float)(n0 + 1);
        #pragma unroll
        for (int it = 0; it < 8; it++) {
            int mid = (lo + hi) >> 1;
            if (cdfc[mid] < rank0) lo = mid + 1; else hi = mid;
        }
        acc = 0.f;
        #pragma unroll
        for (int j = 0; j < 4; j++) {
            const float rank = (float)(n0 + j + 1);
            while (lo < BINS - 1 && cdfc[lo] < rank) lo++;
            const float d = r0s[lo] - xs[j];
            acc += d * d;
        }
    }

    acc = warpSum(acc);
    if (lane == 0) sw_[w] = acc;
    __syncthreads();
    if (t == 0) {
        float s = 0.f;
        #pragma unroll
        for (int i = 0; i < 8; i++) s += sw_[i];
        const float size  = (float)(NCH * NPIX);
        const float scale = __ldcg(&g_msum) * ((float)NCH / (size * size));
        atomicAdd(out, s * scale);    // * WEIGHT (=1.0); out zeroed by K1
    }
}

extern "C" void kernel_launch(void* const* d_in, const int* in_sizes, int n_in,
                              void* d_out, int out_size)
{
    const float* input = (const float*)d_in[0];
    const float* match = (const float*)d_in[1];
    const float* mask  = (const float*)d_in[2];

    k_hist_k<<<NCH * CSEG, 256>>>(input, match, mask, (float*)d_out);

    // PDL secondary: may begin (and prefetch) while K1 is still running.
    cudaLaunchConfig_t cfg = {};
    cfg.gridDim  = dim3(GRID2, 1, 1);
    cfg.blockDim = dim3(256, 1, 1);
    cfg.dynamicSmemBytes = 0;
    cfg.stream = 0;
    cudaLaunchAttribute attr[1];
    attr[0].id = cudaLaunchAttributeProgrammaticStreamSerialization;
    attr[0].val.programmaticStreamSerializationAllowed = 1;
    cfg.attrs = attr;
    cfg.numAttrs = 1;
    cudaLaunchKernelEx(&cfg, k_loss, input, mask, (float*)d_out);
}